// round 15
// baseline (speedup 1.0000x reference)
#include <cuda_runtime.h>

#define DIM 16
#define NLAYERS 3
#define LSTEPS 10
#define TPB 128

typedef unsigned long long u64;

// ---- packed f32x2 helpers (Blackwell sm_103a) ----
__device__ __forceinline__ u64 pk2(float a, float b){
    u64 r; asm("mov.b64 %0, {%1, %2};" : "=l"(r) : "f"(a), "f"(b)); return r;
}
__device__ __forceinline__ void up2(u64 v, float& a, float& b){
    asm("mov.b64 {%0, %1}, %2;" : "=f"(a), "=f"(b) : "l"(v));
}
__device__ __forceinline__ u64 fma2(u64 a, u64 b, u64 c){
    u64 d; asm("fma.rn.f32x2 %0, %1, %2, %3;" : "=l"(d) : "l"(a), "l"(b), "l"(c)); return d;
}
__device__ __forceinline__ u64 add2(u64 a, u64 b){
    u64 d; asm("add.rn.f32x2 %0, %1, %2;" : "=l"(d) : "l"(a), "l"(b)); return d;
}
__device__ __forceinline__ u64 mul2(u64 a, u64 b){
    u64 d; asm("mul.rn.f32x2 %0, %1, %2;" : "=l"(d) : "l"(a), "l"(b)); return d;
}

#define ONE2_C  0x3F8000003F800000ULL
#define NONE2_C 0xBF800000BF800000ULL
#define HALF2_C 0x3F0000003F000000ULL
#define TANHC2_C 0x4038AA3B4038AA3BULL   // 2*log2(e) packed x2

// tanh tail from pre-multiplied z: (e-1)/(e+1), e = 2^z — same chain since R1
__device__ __forceinline__ float ftanh_z(float z){
    z = fminf(z, 126.0f);
    float e; asm("ex2.approx.f32 %0, %1;" : "=f"(e) : "f"(z));
    float r; asm("rcp.approx.f32 %0, %1;" : "=f"(r) : "f"(e + 1.0f));
    return (e - 1.0f) * r;
}

// tanh of a packed pair (packed premul rounds identically to scalar FMUL)
__device__ __forceinline__ void tanh_pair(u64 y2, float& xlo, float& xhi){
    u64 z2 = mul2(y2, TANHC2_C);
    float zlo, zhi; up2(z2, zlo, zhi);
    xlo = ftanh_z(zlo); xhi = ftanh_z(zhi);
}

// Fused-shuffle half-row matvec:
// acc[a] += sum_{k=0..15} x_k * M[k][off+2a .. off+2a+1]
// x_k fetched on the fly: k<8 lives in the even lane's xown[k], k>=8 in the
// odd lane's xown[k-8]. Same source values / mapping / k-ascending fma order
// as the R12-R14 pre-materialized exchange -> bitwise identical, but the
// xl[8]/xh[8] arrays (16 regs) never exist.
__device__ __forceinline__ void matvec_half_fused(const float* __restrict__ Msh, int off,
                                                  const float xown[8],
                                                  int lane_even, int lane_odd,
                                                  u64 acc[4]){
#pragma unroll 4
    for (int k = 0; k < 16; k++){
        float xk = __shfl_sync(0xffffffffu, xown[k & 7], (k < 8) ? lane_even : lane_odd);
        u64 xkp = pk2(xk, xk);
        const ulonglong2* rp = reinterpret_cast<const ulonglong2*>(Msh + k*16 + off);
        ulonglong2 r0 = rp[0], r1 = rp[1];
        acc[0] = fma2(xkp, r0.x, acc[0]); acc[1] = fma2(xkp, r0.y, acc[1]);
        acc[2] = fma2(xkp, r1.x, acc[2]); acc[3] = fma2(xkp, r1.y, acc[3]);
    }
}

// f = (delta + x@M)*(1-x^2) on own 8 components; w precomputed by caller
__device__ __forceinline__ void forcev_half(const float* __restrict__ Msh,
                                            const float* __restrict__ dsh, int off,
                                            const float xown[8],
                                            int lane_even, int lane_odd,
                                            const u64 w[4], u64 f[4]){
    {
        const ulonglong2* dp = reinterpret_cast<const ulonglong2*>(dsh + off);
        ulonglong2 a = dp[0], b = dp[1];
        f[0] = a.x; f[1] = a.y; f[2] = b.x; f[3] = b.y;
    }
    matvec_half_fused(Msh, off, xown, lane_even, lane_odd, f);
#pragma unroll
    for (int a = 0; a < 4; a++)
        f[a] = mul2(f[a], w[a]);
}

// Two threads per row. R14: 80 regs / 24 warps / issue 80.4% with fma & alu
// locked at ~52% (packed f32x2 charges both pipes) -> issue-slot-bound.
// This round: fused-shuffle matvec removes the 16-reg xl/xh transient ->
// target <=73 regs -> (128,7) = 28 warps/SM (+17% issue coverage).
__global__ void __launch_bounds__(TPB, 7)
ising_kernel(const float* __restrict__ Q, const float* __restrict__ delta,
             const float* __restrict__ y0, const float* __restrict__ vn,
             float* __restrict__ xout, float* __restrict__ energy, int B)
{
    __shared__ __align__(16) float Msh[DIM*DIM];
    __shared__ __align__(16) float dsh[DIM];
    int t = threadIdx.x;
#pragma unroll
    for (int idx = t; idx < 256; idx += TPB){
        int i = idx >> 4, j = idx & 15;
        float v = 0.f;
        if (i != j){
            int a = i > j ? i : j, b = i > j ? j : i;
            v = Q[a*(a-1)/2 + b];
        }
        Msh[idx] = v;
    }
    if (t < DIM) dsh[t] = delta[t];
    __syncthreads();

    int gt   = blockIdx.x * TPB + t;
    int row  = gt >> 1;
    int half = gt & 1;
    int off  = half * 8;
    int lane = t & 31;
    int lane_even = lane & ~1;   // even lane of the pair: holds x[0..7]
    int lane_odd  = lane | 1;    // odd lane: holds x[8..15]
    if (row >= B) return;   // never diverges: 2B % TPB == 0 for this problem

    // own 8 components of y0 (coalesced 32B per thread)
    u64 yv[4];
    {
        const ulonglong2* yp = reinterpret_cast<const ulonglong2*>(y0 + (size_t)row*16 + off);
        ulonglong2 a = yp[0], b = yp[1];
        yv[0] = a.x; yv[1] = a.y; yv[2] = b.x; yv[3] = b.y;
    }

    float xown[8];
#pragma unroll
    for (int i = 0; i < 4; i++)
        tanh_pair(yv[i], xown[2*i], xown[2*i+1]);

    u64 f[4];
    {
        u64 w[4];
#pragma unroll
        for (int a = 0; a < 4; a++){
            u64 xp = pk2(xown[2*a], xown[2*a+1]);
            w[a] = fma2(mul2(xp, xp), NONE2_C, ONE2_C);
        }
        forcev_half(Msh, dsh, off, xown, lane_even, lane_odd, w, f);
    }

#pragma unroll 1
    for (int l = 0; l < NLAYERS; l++){
        u64 vel[4];
        {
            const ulonglong2* vp =
                reinterpret_cast<const ulonglong2*>(vn + ((size_t)l * B + row) * 16 + off);
            ulonglong2 a = vp[0], b = vp[1];
            vel[0] = a.x; vel[1] = a.y; vel[2] = b.x; vel[3] = b.y;
        }
#pragma unroll 1
        for (int it = 0; it < LSTEPS; it++){
#pragma unroll
            for (int i = 0; i < 4; i++){
                vel[i] = fma2(f[i], HALF2_C, vel[i]);   // vel + 0.5*f
                yv[i]  = add2(yv[i], vel[i]);           // y += vel_half
            }
            bool last = (l == NLAYERS-1) && (it == LSTEPS-1);
            if (!last){
#pragma unroll
                for (int i = 0; i < 4; i++)
                    tanh_pair(yv[i], xown[2*i], xown[2*i+1]);
                u64 w[4];
#pragma unroll
                for (int a = 0; a < 4; a++){
                    u64 xp = pk2(xown[2*a], xown[2*a+1]);
                    w[a] = fma2(mul2(xp, xp), NONE2_C, ONE2_C);
                }
                forcev_half(Msh, dsh, off, xown, lane_even, lane_odd, w, f);
#pragma unroll
                for (int i = 0; i < 4; i++)
                    vel[i] = fma2(f[i], HALF2_C, vel[i]);  // vel = vel_half + 0.5*f
            }
        }
    }

    // x_out = sign(y) with sign(0) -> -1, own 8 components
    float xo[8];
#pragma unroll
    for (int i = 0; i < 4; i++){
        float lo, hi; up2(yv[i], lo, hi);
        xo[2*i]   = lo > 0.f ? 1.f : -1.f;
        xo[2*i+1] = hi > 0.f ? 1.f : -1.f;
    }
    {
        float4* op = reinterpret_cast<float4*>(xout + (size_t)row*16 + off);
        op[0] = make_float4(xo[0], xo[1], xo[2], xo[3]);
        op[1] = make_float4(xo[4], xo[5], xo[6], xo[7]);
    }

    // energy = sum_j (0.5*(x@M)_j + delta_j)*x_j ; half-sums combined via shfl
    {
        u64 s[4] = {0ULL, 0ULL, 0ULL, 0ULL};
        matvec_half_fused(Msh, off, xo, lane_even, lane_odd, s);
        const ulonglong2* dp = reinterpret_cast<const ulonglong2*>(dsh + off);
        ulonglong2 da = dp[0], db = dp[1];
        u64 dl[4] = {da.x, da.y, db.x, db.y};
        u64 acc = 0ULL;
#pragma unroll
        for (int a = 0; a < 4; a++){
            u64 tj = fma2(s[a], HALF2_C, dl[a]);
            u64 xp = pk2(xo[2*a], xo[2*a+1]);
            acc = fma2(tj, xp, acc);
        }
        float elo, ehi; up2(acc, elo, ehi);
        float part  = elo + ehi;
        float other = __shfl_xor_sync(0xffffffffu, part, 1);
        if (half == 0) energy[row] = part + other;
    }
}

extern "C" void kernel_launch(void* const* d_in, const int* in_sizes, int n_in,
                              void* d_out, int out_size)
{
    // metadata order: inputs(B,1), Q(120), delta(16), y0(B,16), vel_noise(3,B,16)
    const float* Q     = (const float*)d_in[1];
    const float* delta = (const float*)d_in[2];
    const float* y0    = (const float*)d_in[3];
    const float* vn    = (const float*)d_in[4];
    int B = in_sizes[3] / 16;

    float* out    = (float*)d_out;
    float* xout   = out;                      // (B, 16)
    float* energy = out + (size_t)B * 16;     // (B,)

    long long threads = 2LL * B;
    int grid = (int)((threads + TPB - 1) / TPB);
    ising_kernel<<<grid, TPB>>>(Q, delta, y0, vn, xout, energy, B);
}